// round 11
// baseline (speedup 1.0000x reference)
#include <cuda_runtime.h>
#include <math.h>

// Signature-kernel MMD on GB300.  X, Y: (64, 128, 16) fp32, n=0 (f=1). Out: scalar fp32.
// inc = dX_a @ dY_b^T (127x127, K=16);  G[i][j] = G[i][j-1] + G[i-1][j] + G[i-1][j-1]*(inc[i-1][j-1]-1)
// k(a,b) = G[127][127].  Loss = mean kxx + mean kyy - 2 mean kxy (symmetry-deduped).
//
// R10: warp-specialized 3-warp block per pair.
//   warps 0,1: GEMM producers — warp w, lane l computes inc rows 64w+2l, 64w+2l+1
//              into a 48-column smem ring (column-major, pitch 128 floats).
//   warp 2:    DP consumer — lane l owns G rows 4l+1..4l+4, single systolic pass,
//              one LDS.128 + one SHFL per iteration.
// Pipelined per 8-column chunk with one __syncthreads. RING=48 (not 40!):
// concurrent produce-ahead writes slots aliasing cols 8c-40..8c-33, all consumed
// before chunk c starts (lane 31 is at col 8c-32). RING=40 would race.

#define DIM   16
#define NTRI  2080      // 64*65/2
#define NTASK 8256      // 2*NTRI + 4096
#define RING  48

__device__ float g_dX[64 * 128 * DIM];   // row 127 zero-filled
__device__ float g_dY[64 * 128 * DIM];
__device__ float g_part[NTASK];
__device__ unsigned int g_count;         // zero-init; finalizer resets

typedef unsigned long long u64;

__device__ __forceinline__ u64 mul2(u64 a, u64 b) {
    u64 d; asm("mul.rn.f32x2 %0,%1,%2;" : "=l"(d) : "l"(a), "l"(b)); return d;
}
__device__ __forceinline__ u64 fma2(u64 a, u64 b, u64 c) {
    u64 d; asm("fma.rn.f32x2 %0,%1,%2,%3;" : "=l"(d) : "l"(a), "l"(b), "l"(c)); return d;
}
__device__ __forceinline__ u64 add2(u64 a, u64 b) {
    u64 d; asm("add.rn.f32x2 %0,%1,%2;" : "=l"(d) : "l"(a), "l"(b)); return d;
}
__device__ __forceinline__ float hsum2(u64 v) {
    float lo, hi; asm("mov.b64 {%0,%1},%2;" : "=f"(lo), "=f"(hi) : "l"(v));
    return lo + hi;
}

__global__ void sig_prep(const float* __restrict__ X, const float* __restrict__ Y) {
    int idx = blockIdx.x * blockDim.x + threadIdx.x;   // over 64*128*16
    if (idx >= 64 * 128 * DIM) return;
    int d = idx & (DIM - 1);
    int i = (idx >> 4) & 127;
    int a = idx >> 11;
    float vx = 0.0f, vy = 0.0f;
    if (i < 127) {
        int p = a * 128 * DIM + i * DIM + d;
        vx = X[p + DIM] - X[p];
        vy = Y[p + DIM] - Y[p];
    }
    g_dX[idx] = vx;
    g_dY[idx] = vy;
}

__global__ void __launch_bounds__(96, 6) sig_pair(float* __restrict__ out)
{
    __shared__ float sRing[RING * 128];    // 24576 B; col-major, pitch 128 floats

    const int task = blockIdx.x;
    const int tid  = threadIdx.x;
    const int wid  = tid >> 5;
    const int lane = tid & 31;

    // ---- decode task -> (dxP, dyP, weight) ----
    const float *dxP, *dyP;
    float w;
    if (task < 2 * NTRI) {
        int u = task;
        const float* P = g_dX;
        if (u >= NTRI) { u -= NTRI; P = g_dY; }
        int aa = (int)((129.0f - sqrtf(16641.0f - 8.0f * (float)u)) * 0.5f);
        if (aa < 0) aa = 0;
        if (aa > 63) aa = 63;
        while (aa > 0 && aa * (129 - aa) / 2 > u) --aa;
        while (aa < 63 && (aa + 1) * (128 - aa) / 2 <= u) ++aa;
        int b = aa + (u - aa * (129 - aa) / 2);
        dxP = P + aa * 128 * DIM;
        dyP = P + b  * 128 * DIM;
        w = (aa == b) ? 1.0f : 2.0f;
    } else {
        int u = task - 2 * NTRI;
        dxP = g_dX + (u >> 6) * 128 * DIM;
        dyP = g_dY + (u & 63) * 128 * DIM;
        w = -2.0f;
    }

    // ---- GEMM state (warps 0,1): lane owns inc rows r0, r0+1 ----
    u64 dxp[16];
    const int sbase = 64 * wid + 2 * lane;       // float offset of r0 in a ring column
    if (wid < 2) {
        const ulonglong2* p0 = (const ulonglong2*)(dxP + sbase * DIM);
        const ulonglong2* p1 = (const ulonglong2*)(dxP + (sbase + 1) * DIM);
        #pragma unroll
        for (int k = 0; k < 4; ++k) {
            ulonglong2 v0 = p0[k], v1 = p1[k];
            dxp[2 * k]     = v0.x; dxp[2 * k + 1]     = v0.y;
            dxp[8 + 2 * k] = v1.x; dxp[8 + 2 * k + 1] = v1.y;
        }
    }

    // produce 8 inc columns col0..col0+7 into ring slots slot0..slot0+7
    #define PRODUCE8(col0, slot0) do {                                         \
        const float* dy = dyP + (col0) * DIM;                                  \
        _Pragma("unroll")                                                      \
        for (int jj = 0; jj < 8; ++jj) {                                       \
            const ulonglong2* yp = (const ulonglong2*)(dy + jj * DIM);         \
            ulonglong2 ya = yp[0], yb = yp[1], yc = yp[2], yd = yp[3];         \
            u64 ta = mul2(dxp[0], ya.x);                                       \
            u64 tb = mul2(dxp[1], ya.y);                                       \
            ta = fma2(dxp[2], yb.x, ta);                                       \
            tb = fma2(dxp[3], yb.y, tb);                                       \
            ta = fma2(dxp[4], yc.x, ta);                                       \
            tb = fma2(dxp[5], yc.y, tb);                                       \
            ta = fma2(dxp[6], yd.x, ta);                                       \
            tb = fma2(dxp[7], yd.y, tb);                                       \
            float d0 = hsum2(add2(ta, tb));                                    \
            u64 ua = mul2(dxp[8], ya.x);                                       \
            u64 ub = mul2(dxp[9], ya.y);                                       \
            ua = fma2(dxp[10], yb.x, ua);                                      \
            ub = fma2(dxp[11], yb.y, ub);                                      \
            ua = fma2(dxp[12], yc.x, ua);                                      \
            ub = fma2(dxp[13], yc.y, ub);                                      \
            ua = fma2(dxp[14], yd.x, ua);                                      \
            ub = fma2(dxp[15], yd.y, ub);                                      \
            float d1 = hsum2(add2(ua, ub));                                    \
            *(float2*)(sRing + ((slot0) + jj) * 128 + sbase) =                 \
                make_float2(d0, d1);                                           \
        }                                                                      \
    } while (0)

    // ---- DP state (warp 2): lane owns G rows 4l+1..4l+4 ----
    const int rbase = 4 * lane;
    float gr0 = 1.0f, gr1 = 1.0f, gr2 = 1.0f, gr3 = 1.0f;
    float up = 1.0f, up_prev = 1.0f;             // G[4l][j], G[4l][j-1]
    int rj = (lane == 0) ? 0 : (RING - lane);    // slot of col (m - lane) mod RING
    int m = 0;

    #define DP_ITER do {                                                       \
        bool act = ((unsigned)(m - lane) <= 126u);                             \
        float4 iv = *(const float4*)(sRing + rj * 128 + rbase);                \
        float u0 = fmaf(up_prev, iv.x, gr0 - up_prev);                         \
        float u1 = fmaf(gr0, iv.y, gr1 - gr0);                                 \
        float u2 = fmaf(gr1, iv.z, gr2 - gr1);                                 \
        float u3 = fmaf(gr2, iv.w, gr3 - gr2);                                 \
        float n0 = u0 + up;                                                    \
        float n1 = u1 + n0;                                                    \
        float n2 = u2 + n1;                                                    \
        float n3 = u3 + n2;                                                    \
        if (act) { gr0 = n0; gr1 = n1; gr2 = n2; gr3 = n3; up_prev = up; }     \
        float snd = __shfl_up_sync(0xffffffffu, gr3, 1);                       \
        up = (lane == 0) ? 1.0f : snd;                                         \
        rj = (rj + 1 == RING) ? 0 : rj + 1;                                    \
        ++m;                                                                   \
    } while (0)

    // ---- pipelined schedule: produce chunk c+1 while DP consumes chunk c ----
    if (wid < 2) PRODUCE8(0, 0);                 // chunk 0: cols 0..7
    __syncthreads();
    for (int c = 0; c < 16; ++c) {
        if (wid < 2) {
            if (c < 15) {
                int col0 = 8 * (c + 1);
                PRODUCE8(col0, col0 % RING);     // slots 8,16,24,32,40,0,8,...
            }
        } else if (wid == 2) {
            #pragma unroll
            for (int k = 0; k < 8; ++k) DP_ITER; // m = 8c .. 8c+7
        }
        __syncthreads();
    }

    if (wid == 2) {
        #pragma unroll 2
        for (int t = 0; t < 30; ++t) DP_ITER;    // m = 128..157 (drain)

        // lane 31 rows 125..128 -> gr2 holds G[127][127]
        if (lane == 31)
            g_part[task] = w * gr2 * (1.0f / 4096.0f);

        // ---- last block reduces all partials -> out ----
        __threadfence();
        unsigned int done = 0;
        if (lane == 0) done = atomicAdd(&g_count, 1u);
        done = __shfl_sync(0xffffffffu, done, 0);
        if (done == NTASK - 1) {
            __threadfence();
            double sum = 0.0;
            #pragma unroll 4
            for (int i = lane; i < NTASK; i += 32) sum += (double)g_part[i];
            #pragma unroll
            for (int off = 16; off > 0; off >>= 1)
                sum += __shfl_down_sync(0xffffffffu, sum, off);
            if (lane == 0) {
                out[0] = (float)sum;
                atomicExch(&g_count, 0u);        // reset for next graph replay
            }
        }
    }
}

extern "C" void kernel_launch(void* const* d_in, const int* in_sizes, int n_in,
                              void* d_out, int out_size)
{
    const float* X = (const float*)d_in[0];
    const float* Y = (const float*)d_in[1];
    (void)in_sizes; (void)n_in; (void)out_size;

    cudaFuncSetAttribute(sig_pair, cudaFuncAttributePreferredSharedMemoryCarveout, 100);

    sig_prep<<<(64 * 128 * DIM + 255) / 256, 256>>>(X, Y);
    sig_pair<<<NTASK, 96>>>((float*)d_out);
}

// round 14
// speedup vs baseline: 1.2248x; 1.2248x over previous
#include <cuda_runtime.h>
#include <math.h>

// Signature-kernel MMD on GB300.  X, Y: (64, 128, 16) fp32, n=0 (f=1). Out: scalar fp32.
// inc = dX_a @ dY_b^T (127x127, K=16);  G[i][j] = G[i][j-1] + G[i-1][j] + G[i-1][j-1]*(inc[i-1][j-1]-1)
// k(a,b) = G[127][127].  Loss = mean kxx + mean kyy - 2 mean kxy (symmetry-deduped).
//
// R12 = R8 base (one warp per pair, sequential produce/consume, no block barriers)
//  + row-pair f32x2 packing: dX packed as (row_r, row_{r+1}) pairs, dY duplicated
//    (v,v) in scratch -> each dot product lands already packed as
//    (inc[r][j], inc[r+1][j]); no hsum, single STS.128 per 4 rows.
//  + chunk 4 / RING 36 -> smem 18.4 KB -> 12 blocks/SM.
// Ring col-major pitch 128 floats: STS.128/LDS.128 at 4*lane -> conflict-free.
// Ring safety (sequential): producing cols 4c..4c+3 aliases cols 4c-36..4c-33;
// lane 31 has consumed through col 4c-32 before the produce -> safe.

#define DIM   16
#define NTRI  2080      // 64*65/2
#define NTASK 8256      // 2*NTRI + 4096
#define RING  36

typedef unsigned long long u64;

__device__ float g_dX[64 * 128 * DIM];   // plain increments, row 127 zero
__device__ float g_dY[64 * 128 * DIM];
__device__ u64   g_dXd[64 * 128 * DIM];  // duplicated (v,v) pairs
__device__ u64   g_dYd[64 * 128 * DIM];
__device__ float g_part[NTASK];
__device__ unsigned int g_count;         // zero-init; finalizer resets

__device__ __forceinline__ u64 mul2(u64 a, u64 b) {
    u64 d; asm("mul.rn.f32x2 %0,%1,%2;" : "=l"(d) : "l"(a), "l"(b)); return d;
}
__device__ __forceinline__ u64 fma2(u64 a, u64 b, u64 c) {
    u64 d; asm("fma.rn.f32x2 %0,%1,%2,%3;" : "=l"(d) : "l"(a), "l"(b), "l"(c)); return d;
}
__device__ __forceinline__ u64 add2(u64 a, u64 b) {
    u64 d; asm("add.rn.f32x2 %0,%1,%2;" : "=l"(d) : "l"(a), "l"(b)); return d;
}
__device__ __forceinline__ u64 pack2(float lo, float hi) {
    u64 r; asm("mov.b64 %0,{%1,%2};" : "=l"(r) : "f"(lo), "f"(hi)); return r;
}

__global__ void sig_prep(const float* __restrict__ X, const float* __restrict__ Y) {
    int idx = blockIdx.x * blockDim.x + threadIdx.x;   // over 64*128*16
    if (idx >= 64 * 128 * DIM) return;
    int d = idx & (DIM - 1);
    int i = (idx >> 4) & 127;
    int a = idx >> 11;
    float vx = 0.0f, vy = 0.0f;
    if (i < 127) {
        int p = a * 128 * DIM + i * DIM + d;
        vx = X[p + DIM] - X[p];
        vy = Y[p + DIM] - Y[p];
    }
    g_dX[idx] = vx;
    g_dY[idx] = vy;
    g_dXd[idx] = pack2(vx, vx);
    g_dYd[idx] = pack2(vy, vy);
}

__global__ void __launch_bounds__(32, 12) sig_pair(float* __restrict__ out)
{
    __shared__ float sRing[RING * 128];    // 18432 B; col-major, pitch 128 floats

    const int task = blockIdx.x;
    const int lane = threadIdx.x;

    // ---- decode task -> (dxP plain, dydP duplicated, weight) ----
    const float* dxP;
    const u64*   dydP;
    float w;
    if (task < 2 * NTRI) {
        int u = task;
        const float* Pp = g_dX;
        const u64*   Pd = g_dXd;
        if (u >= NTRI) { u -= NTRI; Pp = g_dY; Pd = g_dYd; }
        int aa = (int)((129.0f - sqrtf(16641.0f - 8.0f * (float)u)) * 0.5f);
        if (aa < 0) aa = 0;
        if (aa > 63) aa = 63;
        while (aa > 0 && aa * (129 - aa) / 2 > u) --aa;
        while (aa < 63 && (aa + 1) * (128 - aa) / 2 <= u) ++aa;
        int b = aa + (u - aa * (129 - aa) / 2);
        dxP  = Pp + aa * 128 * DIM;
        dydP = Pd + b  * 128 * DIM;
        w = (aa == b) ? 1.0f : 2.0f;
    } else {
        int u = task - 2 * NTRI;
        dxP  = g_dX  + (u >> 6) * 128 * DIM;
        dydP = g_dYd + (u & 63) * 128 * DIM;
        w = -2.0f;
    }

    // ---- pack dX rows 4l..4l+3 as row-pairs: d01[k]=(r0[k],r1[k]), d23[k]=(r2[k],r3[k])
    u64 d01[16], d23[16];
    {
        const float* xr = dxP + (4 * lane) * DIM;    // 64 consecutive floats
        float r0[16], r1[16], r2[16], r3[16];
        #pragma unroll
        for (int q = 0; q < 4; ++q) {
            *(float4*)&r0[4 * q] = ((const float4*)(xr))[q];
            *(float4*)&r1[4 * q] = ((const float4*)(xr + DIM))[q];
            *(float4*)&r2[4 * q] = ((const float4*)(xr + 2 * DIM))[q];
            *(float4*)&r3[4 * q] = ((const float4*)(xr + 3 * DIM))[q];
        }
        #pragma unroll
        for (int k = 0; k < 16; ++k) {
            d01[k] = pack2(r0[k], r1[k]);
            d23[k] = pack2(r2[k], r3[k]);
        }
    }

    const int rbase = 4 * lane;            // this lane's 16B slice of each ring column

    // produce 4 inc columns col0..col0+3 into ring slots slot0..slot0+3
    #define PRODUCE4(col0, slot0) do {                                         \
        const ulonglong2* ydc = (const ulonglong2*)(dydP + (col0) * DIM);      \
        _Pragma("unroll")                                                      \
        for (int jj = 0; jj < 4; ++jj) {                                       \
            const ulonglong2* yp = ydc + jj * 8;   /* 16 u64 per col */        \
            ulonglong2 q0 = yp[0], q1 = yp[1], q2 = yp[2], q3 = yp[3];         \
            ulonglong2 q4 = yp[4], q5 = yp[5], q6 = yp[6], q7 = yp[7];         \
            u64 a0 = mul2(d01[0], q0.x);                                       \
            u64 a1 = mul2(d01[1], q0.y);                                       \
            a0 = fma2(d01[2],  q1.x, a0);  a1 = fma2(d01[3],  q1.y, a1);       \
            a0 = fma2(d01[4],  q2.x, a0);  a1 = fma2(d01[5],  q2.y, a1);       \
            a0 = fma2(d01[6],  q3.x, a0);  a1 = fma2(d01[7],  q3.y, a1);       \
            a0 = fma2(d01[8],  q4.x, a0);  a1 = fma2(d01[9],  q4.y, a1);       \
            a0 = fma2(d01[10], q5.x, a0);  a1 = fma2(d01[11], q5.y, a1);       \
            a0 = fma2(d01[12], q6.x, a0);  a1 = fma2(d01[13], q6.y, a1);       \
            a0 = fma2(d01[14], q7.x, a0);  a1 = fma2(d01[15], q7.y, a1);       \
            u64 b0 = mul2(d23[0], q0.x);                                       \
            u64 b1 = mul2(d23[1], q0.y);                                       \
            b0 = fma2(d23[2],  q1.x, b0);  b1 = fma2(d23[3],  q1.y, b1);       \
            b0 = fma2(d23[4],  q2.x, b0);  b1 = fma2(d23[5],  q2.y, b1);       \
            b0 = fma2(d23[6],  q3.x, b0);  b1 = fma2(d23[7],  q3.y, b1);       \
            b0 = fma2(d23[8],  q4.x, b0);  b1 = fma2(d23[9],  q4.y, b1);       \
            b0 = fma2(d23[10], q5.x, b0);  b1 = fma2(d23[11], q5.y, b1);       \
            b0 = fma2(d23[12], q6.x, b0);  b1 = fma2(d23[13], q6.y, b1);       \
            b0 = fma2(d23[14], q7.x, b0);  b1 = fma2(d23[15], q7.y, b1);       \
            ulonglong2 st;                                                     \
            st.x = add2(a0, a1);   /* (inc[4l][j], inc[4l+1][j]) */            \
            st.y = add2(b0, b1);   /* (inc[4l+2][j], inc[4l+3][j]) */          \
            *(ulonglong2*)(sRing + ((slot0) + jj) * 128 + rbase) = st;         \
        }                                                                      \
    } while (0)

    // ---- DP state: lane l owns G rows 4l+1..4l+4 ----
    float gr0 = 1.0f, gr1 = 1.0f, gr2 = 1.0f, gr3 = 1.0f;
    float up = 1.0f, up_prev = 1.0f;             // G[4l][j], G[4l][j-1]
    int rj = (lane == 0) ? 0 : (RING - lane);    // slot of col (m - lane) mod RING
    int m = 0;

    #define DP_ITER do {                                                       \
        bool act = ((unsigned)(m - lane) <= 126u);                             \
        float4 iv = *(const float4*)(sRing + rj * 128 + rbase);                \
        float u0 = fmaf(up_prev, iv.x, gr0 - up_prev);                         \
        float u1 = fmaf(gr0, iv.y, gr1 - gr0);                                 \
        float u2 = fmaf(gr1, iv.z, gr2 - gr1);                                 \
        float u3 = fmaf(gr2, iv.w, gr3 - gr2);                                 \
        float n0 = u0 + up;                                                    \
        float n1 = u1 + n0;                                                    \
        float n2 = u2 + n1;                                                    \
        float n3 = u3 + n2;                                                    \
        if (act) { gr0 = n0; gr1 = n1; gr2 = n2; gr3 = n3; up_prev = up; }     \
        float snd = __shfl_up_sync(0xffffffffu, gr3, 1);                       \
        up = (lane == 0) ? 1.0f : snd;                                         \
        rj = (rj + 1 == RING) ? 0 : rj + 1;                                    \
        ++m;                                                                   \
    } while (0)

    // ---- sequential in-warp schedule: consume 4, produce next 4 ----
    PRODUCE4(0, 0);                              // cols 0..3
    int slotc = 4;
    for (int c = 1; c < 32; ++c) {
        #pragma unroll
        for (int k = 0; k < 4; ++k) DP_ITER;     // m = 4(c-1) .. 4(c-1)+3
        PRODUCE4(4 * c, slotc);
        slotc += 4; if (slotc >= RING) slotc -= RING;
    }
    #pragma unroll 2
    for (int t = 0; t < 34; ++t) DP_ITER;        // m = 124..157 (drain)

    // lane 31 rows 125..128 -> gr2 holds G[127][127]
    if (lane == 31)
        g_part[task] = w * gr2 * (1.0f / 4096.0f);

    // ---- last block reduces all partials -> out ----
    __threadfence();
    unsigned int done = 0;
    if (lane == 0) done = atomicAdd(&g_count, 1u);
    done = __shfl_sync(0xffffffffu, done, 0);
    if (done == NTASK - 1) {
        __threadfence();
        double sum = 0.0;
        #pragma unroll 4
        for (int i = lane; i < NTASK; i += 32) sum += (double)g_part[i];
        #pragma unroll
        for (int off = 16; off > 0; off >>= 1)
            sum += __shfl_down_sync(0xffffffffu, sum, off);
        if (lane == 0) {
            out[0] = (float)sum;
            atomicExch(&g_count, 0u);            // reset for next graph replay
        }
    }
}

extern "C" void kernel_launch(void* const* d_in, const int* in_sizes, int n_in,
                              void* d_out, int out_size)
{
    const float* X = (const float*)d_in[0];
    const float* Y = (const float*)d_in[1];
    (void)in_sizes; (void)n_in; (void)out_size;

    cudaFuncSetAttribute(sig_pair, cudaFuncAttributePreferredSharedMemoryCarveout, 100);

    sig_prep<<<(64 * 128 * DIM + 255) / 256, 256>>>(X, Y);
    sig_pair<<<NTASK, 32>>>((float*)d_out);
}

// round 15
// speedup vs baseline: 1.4399x; 1.1756x over previous
#include <cuda_runtime.h>
#include <math.h>

// Signature-kernel MMD on GB300.  X, Y: (64, 128, 16) fp32, n=0 (f=1). Out: scalar fp32.
// inc = dX_a @ dY_b^T (127x127, K=16);  G[i][j] = G[i][j-1] + G[i-1][j] + G[i-1][j-1]*(inc[i-1][j-1]-1)
// k(a,b) = G[127][127].  Loss = mean kxx + mean kyy - 2 mean kxy (symmetry-deduped).
//
// R15 = one warp per pair, sequential produce/consume, no block barriers.
//  GEMM: natural f32x2 packing + hsum (4 uniform LDG.128/col, wf-optimal);
//        accumulators seeded with (-0.5,-0.5) so the ring holds (inc-1) for free.
//  DP:   lane l owns G rows 4l+1..4l+4; per iter 1 LDS.128 + 1 SHFL,
//        4 FFMA + 4 FADD (no subs).  Fast unpredicated body for m in [32,123].
//  chunk 4 / RING 36 -> smem 18.4 KB -> 12 blocks/SM.
// Ring safety (sequential): producing cols 4c..4c+3 aliases cols 4c-36..4c-33;
// lane 31 has consumed through col 4c-32 before the produce -> safe.

#define DIM   16
#define NTRI  2080      // 64*65/2
#define NTASK 8256      // 2*NTRI + 4096
#define RING  36

typedef unsigned long long u64;

__device__ float g_dX[64 * 128 * DIM];   // increments, row 127 zero
__device__ float g_dY[64 * 128 * DIM];
__device__ float g_part[NTASK];
__device__ unsigned int g_count;         // zero-init; finalizer resets

__device__ __forceinline__ u64 fma2(u64 a, u64 b, u64 c) {
    u64 d; asm("fma.rn.f32x2 %0,%1,%2,%3;" : "=l"(d) : "l"(a), "l"(b), "l"(c)); return d;
}
__device__ __forceinline__ u64 pack2(float lo, float hi) {
    u64 r; asm("mov.b64 %0,{%1,%2};" : "=l"(r) : "f"(lo), "f"(hi)); return r;
}
__device__ __forceinline__ float hsum2(u64 v) {
    float lo, hi; asm("mov.b64 {%0,%1},%2;" : "=f"(lo), "=f"(hi) : "l"(v));
    return lo + hi;
}

__global__ void sig_prep(const float* __restrict__ X, const float* __restrict__ Y) {
    int idx = blockIdx.x * blockDim.x + threadIdx.x;   // over 64*128*16
    if (idx >= 64 * 128 * DIM) return;
    int d = idx & (DIM - 1);
    int i = (idx >> 4) & 127;
    int a = idx >> 11;
    float vx = 0.0f, vy = 0.0f;
    if (i < 127) {
        int p = a * 128 * DIM + i * DIM + d;
        vx = X[p + DIM] - X[p];
        vy = Y[p + DIM] - Y[p];
    }
    g_dX[idx] = vx;
    g_dY[idx] = vy;
}

__global__ void __launch_bounds__(32, 12) sig_pair(float* __restrict__ out)
{
    __shared__ float sRing[RING * 128];    // 18432 B; col-major, pitch 128 floats

    const int task = blockIdx.x;
    const int lane = threadIdx.x;

    // ---- decode task -> (dxP, dyP, weight) ----
    const float *dxP, *dyP;
    float w;
    if (task < 2 * NTRI) {
        int u = task;
        const float* P = g_dX;
        if (u >= NTRI) { u -= NTRI; P = g_dY; }
        int aa = (int)((129.0f - sqrtf(16641.0f - 8.0f * (float)u)) * 0.5f);
        if (aa < 0) aa = 0;
        if (aa > 63) aa = 63;
        while (aa > 0 && aa * (129 - aa) / 2 > u) --aa;
        while (aa < 63 && (aa + 1) * (128 - aa) / 2 <= u) ++aa;
        int b = aa + (u - aa * (129 - aa) / 2);
        dxP = P + aa * 128 * DIM;
        dyP = P + b  * 128 * DIM;
        w = (aa == b) ? 1.0f : 2.0f;
    } else {
        int u = task - 2 * NTRI;
        dxP = g_dX + (u >> 6) * 128 * DIM;
        dyP = g_dY + (u & 63) * 128 * DIM;
        w = -2.0f;
    }

    // ---- lane-private dX rows 4l..4l+3, natural (v0,v1) u64 pairs ----
    u64 dxp[32];                           // dxp[r*8+k] = (row[2k], row[2k+1])
    #pragma unroll
    for (int r = 0; r < 4; ++r) {
        const u64* p = (const u64*)(dxP + (4 * lane + r) * DIM);
        #pragma unroll
        for (int k = 0; k < 8; ++k) dxp[r * 8 + k] = p[k];
    }

    const u64 cNH = pack2(-0.5f, -0.5f);   // accumulator seed: result = dot - 1
    const int rbase = 4 * lane;            // this lane's 16B slice of each ring column

    // produce 4 (inc-1) columns col0..col0+3 into ring slots slot0..slot0+3
    #define PRODUCE4(col0, slot0) do {                                         \
        const ulonglong2* yd = (const ulonglong2*)(dyP + (col0) * DIM);        \
        _Pragma("unroll")                                                      \
        for (int jj = 0; jj < 4; ++jj) {                                       \
            ulonglong2 ya = yd[jj * 4 + 0];    /* (v0,v1),(v2,v3) */           \
            ulonglong2 yb = yd[jj * 4 + 1];                                    \
            ulonglong2 yc = yd[jj * 4 + 2];                                    \
            ulonglong2 ye = yd[jj * 4 + 3];                                    \
            float dd[4];                                                       \
            _Pragma("unroll")                                                  \
            for (int r = 0; r < 4; ++r) {                                      \
                u64 acc = fma2(dxp[r * 8 + 0], ya.x, cNH);                     \
                acc = fma2(dxp[r * 8 + 1], ya.y, acc);                         \
                acc = fma2(dxp[r * 8 + 2], yb.x, acc);                         \
                acc = fma2(dxp[r * 8 + 3], yb.y, acc);                         \
                acc = fma2(dxp[r * 8 + 4], yc.x, acc);                         \
                acc = fma2(dxp[r * 8 + 5], yc.y, acc);                         \
                acc = fma2(dxp[r * 8 + 6], ye.x, acc);                         \
                acc = fma2(dxp[r * 8 + 7], ye.y, acc);                         \
                dd[r] = hsum2(acc);        /* = inc[4l+r][col] - 1 */          \
            }                                                                  \
            *(float4*)(sRing + ((slot0) + jj) * 128 + rbase) =                 \
                make_float4(dd[0], dd[1], dd[2], dd[3]);                       \
        }                                                                      \
    } while (0)

    // ---- DP state: lane l owns G rows 4l+1..4l+4 ----
    float gr0 = 1.0f, gr1 = 1.0f, gr2 = 1.0f, gr3 = 1.0f;
    float up = 1.0f, up_prev = 1.0f;             // G[4l][j], G[4l][j-1]
    int rj = (lane == 0) ? 0 : (RING - lane);    // slot of col (m - lane) mod RING
    int m = 0;

    // Predicated iteration (head / tail lanes may be inactive).
    #define DP_ITER do {                                                       \
        bool act = ((unsigned)(m - lane) <= 126u);                             \
        float4 iv = *(const float4*)(sRing + rj * 128 + rbase);                \
        float n0 = fmaf(up_prev, iv.x, gr0) + up;                              \
        float n1 = fmaf(gr0, iv.y, gr1) + n0;                                  \
        float n2 = fmaf(gr1, iv.z, gr2) + n1;                                  \
        float n3 = fmaf(gr2, iv.w, gr3) + n2;                                  \
        if (act) { gr0 = n0; gr1 = n1; gr2 = n2; gr3 = n3; up_prev = up; }     \
        float snd = __shfl_up_sync(0xffffffffu, gr3, 1);                       \
        up = (lane == 0) ? 1.0f : snd;                                         \
        rj = (rj + 1 == RING) ? 0 : rj + 1;                                    \
        ++m;                                                                   \
    } while (0)

    // Unpredicated iteration: valid only when ALL lanes active (31 <= m <= 126).
    #define DP_ITER_FAST do {                                                  \
        float4 iv = *(const float4*)(sRing + rj * 128 + rbase);                \
        float n0 = fmaf(up_prev, iv.x, gr0) + up;                              \
        float n1 = fmaf(gr0, iv.y, gr1) + n0;                                  \
        float n2 = fmaf(gr1, iv.z, gr2) + n1;                                  \
        float n3 = fmaf(gr2, iv.w, gr3) + n2;                                  \
        gr0 = n0; gr1 = n1; gr2 = n2; gr3 = n3; up_prev = up;                  \
        float snd = __shfl_up_sync(0xffffffffu, gr3, 1);                       \
        up = (lane == 0) ? 1.0f : snd;                                         \
        rj = (rj + 1 == RING) ? 0 : rj + 1;                                    \
        ++m;                                                                   \
    } while (0)

    // ---- sequential in-warp schedule: consume 4, produce next 4 ----
    PRODUCE4(0, 0);                              // cols 0..3
    int slotc = 4;
    for (int c = 1; c <= 8; ++c) {               // m = 0..31 (head, predicated)
        #pragma unroll
        for (int k = 0; k < 4; ++k) DP_ITER;
        PRODUCE4(4 * c, slotc);
        slotc += 4; if (slotc >= RING) slotc -= RING;
    }
    for (int c = 9; c < 32; ++c) {               // m = 32..123 (all lanes active)
        #pragma unroll
        for (int k = 0; k < 4; ++k) DP_ITER_FAST;
        PRODUCE4(4 * c, slotc);
        slotc += 4; if (slotc >= RING) slotc -= RING;
    }
    #pragma unroll 2
    for (int t = 0; t < 34; ++t) DP_ITER;        // m = 124..157 (drain, predicated)

    // lane 31 rows 125..128 -> gr2 holds G[127][127]
    if (lane == 31)
        g_part[task] = w * gr2 * (1.0f / 4096.0f);

    // ---- last block reduces all partials -> out ----
    __threadfence();
    unsigned int done = 0;
    if (lane == 0) done = atomicAdd(&g_count, 1u);
    done = __shfl_sync(0xffffffffu, done, 0);
    if (done == NTASK - 1) {
        __threadfence();
        double sum = 0.0;
        #pragma unroll 4
        for (int i = lane; i < NTASK; i += 32) sum += (double)g_part[i];
        #pragma unroll
        for (int off = 16; off > 0; off >>= 1)
            sum += __shfl_down_sync(0xffffffffu, sum, off);
        if (lane == 0) {
            out[0] = (float)sum;
            atomicExch(&g_count, 0u);            // reset for next graph replay
        }
    }
}

extern "C" void kernel_launch(void* const* d_in, const int* in_sizes, int n_in,
                              void* d_out, int out_size)
{
    const float* X = (const float*)d_in[0];
    const float* Y = (const float*)d_in[1];
    (void)in_sizes; (void)n_in; (void)out_size;

    cudaFuncSetAttribute(sig_pair, cudaFuncAttributePreferredSharedMemoryCarveout, 100);

    sig_prep<<<(64 * 128 * DIM + 255) / 256, 256>>>(X, Y);
    sig_pair<<<NTASK, 32>>>((float*)d_out);
}